// round 9
// baseline (speedup 1.0000x reference)
#include <cuda_runtime.h>
#include <cuda_bf16.h>
#include <math.h>
#include <stdint.h>

#define HWSZ 16384
#define NPIX 32768
#define CC 256

// ---------------- static device scratch ----------------
__device__ __align__(16) __nv_bfloat16 g_faT[2 * HWSZ * CC];     // feat_A NHWC bf16
__device__ __align__(16) __nv_bfloat16 g_fbT[2 * HWSZ * CC];     // feat_B NHWC bf16
__device__ __align__(16) __nv_bfloat16 g_w1k[13 * 4096];         // enc1 W [chunk][oc][k64]
__device__ __align__(16) __nv_bfloat16 g_wck[2][9 * 4096];       // conv W [tap][oc][ci]
__device__ __align__(16) float g_h1[(size_t)NPIX * 64];          // raw layer out ping
__device__ __align__(16) float g_h2[(size_t)NPIX * 64];          // raw layer out pong
__device__ float g_gns[128];
__device__ float g_gnt[128];
__device__ float g_pcs[256 * 64];
__device__ float g_pcs2[256 * 64];

__device__ __forceinline__ float clean15(float v) {
    if (!(v == v)) return 0.f;
    return fminf(fmaxf(v, -1.5f), 1.5f);
}
__device__ __forceinline__ float geluf(float z) {
    return 0.5f * z * (1.f + erff(z * 0.70710678118654752f));
}
__device__ __forceinline__ uint32_t smem_u32(const void* p) {
    uint32_t r;
    asm("{ .reg .u64 t; cvta.to.shared.u64 t, %1; cvt.u32.u64 %0, t; }" : "=r"(r) : "l"(p));
    return r;
}
__device__ __forceinline__ void cp16(uint32_t dst, const void* src) {
    asm volatile("cp.async.cg.shared.global [%0], [%1], 16;" :: "r"(dst), "l"(src));
}
__device__ __forceinline__ void cp_commit() {
    asm volatile("cp.async.commit_group;" ::: "memory");
}
template <int N>
__device__ __forceinline__ void cp_wait() {
    asm volatile("cp.async.wait_group %0;" :: "n"(N) : "memory");
}

// bf16 HMMA: D(16x8,f32) += A(16x16,bf16) * B(8x16,bf16)^T
__device__ __forceinline__ void mma16816(float* d, const uint32_t* a, const uint32_t* b) {
    asm volatile(
        "mma.sync.aligned.m16n8k16.row.col.f32.bf16.bf16.f32 "
        "{%0,%1,%2,%3}, {%4,%5,%6,%7}, {%8,%9}, {%0,%1,%2,%3};"
        : "+f"(d[0]), "+f"(d[1]), "+f"(d[2]), "+f"(d[3])
        : "r"(a[0]), "r"(a[1]), "r"(a[2]), "r"(a[3]), "r"(b[0]), "r"(b[1]));
}

// ---------------- K0: NCHW fp32 -> NHWC bf16 transpose ----------------
__global__ void k_transpose(const float* __restrict__ fA, const float* __restrict__ fB) {
    __shared__ float tile[64][33];
    int z = blockIdx.z;
    const float* src = (z >= 2) ? fB : fA;
    int b = z & 1;
    src += (size_t)b * CC * HWSZ;
    __nv_bfloat16* dstbase = ((z < 2) ? g_faT : g_fbT) + ((size_t)(b << 14) << 8);
    int hw0 = blockIdx.x * 32, c0 = blockIdx.y * 64;
    int tx = threadIdx.x, ty = threadIdx.y;          // (32,8)
#pragma unroll
    for (int i = 0; i < 8; i++) {
        int cr = ty + i * 8;
        tile[cr][tx] = src[(c0 + cr) * HWSZ + hw0 + tx];
    }
    __syncthreads();
#pragma unroll
    for (int i = 0; i < 4; i++) {
        int r = ty + i * 8;
        __nv_bfloat162 v = __floats2bfloat162_rn(tile[2 * tx][r], tile[2 * tx + 1][r]);
        *(__nv_bfloat162*)(dstbase + (size_t)(hw0 + r) * CC + c0 + 2 * tx) = v;
    }
}

// ---------------- weight prep ----------------
__global__ void k_wprep(const float* __restrict__ w1, const float* __restrict__ w2,
                        const float* __restrict__ w3) {
    int blk = blockIdx.x;
    if (blk < 208) {
        int idx = blk * 256 + threadIdx.x;
        if (idx >= 13 * 4096) return;
        int chunk = idx >> 12, rem = idx & 4095;
        int oc = rem >> 6, k = rem & 63;
        int kg = chunk * 64 + k;
        g_w1k[idx] = __float2bfloat16((kg < 780) ? w1[oc * 780 + kg] : 0.f);
    } else {
        int which = (blk < 352) ? 0 : 1;
        const float* w = which ? w3 : w2;
        int idx = (blk - (which ? 352 : 208)) * 256 + threadIdx.x;
        if (idx >= 9 * 4096) return;
        int tap = idx >> 12, rem = idx & 4095;
        int oc = rem >> 6, ci = rem & 63;
        g_wck[which][idx] = __float2bfloat16(w[(oc * 64 + ci) * 9 + tap]);
    }
}

// ---------------- shared epilogue: per-CTA (sum, sumsq) per channel ----------------
#define STATS_EPILOGUE(ACC, SRED, SRED2, SLOT)                                        \
    {                                                                                 \
        float ps[4][2], pq[4][2];                                                     \
        _Pragma("unroll")                                                             \
        for (int nt = 0; nt < 4; nt++) {                                              \
            float v0 = ACC[0][nt][0], v1 = ACC[0][nt][2],                             \
                  v2 = ACC[1][nt][0], v3 = ACC[1][nt][2];                             \
            ps[nt][0] = v0 + v1 + v2 + v3;                                            \
            pq[nt][0] = v0 * v0 + v1 * v1 + v2 * v2 + v3 * v3;                        \
            float u0 = ACC[0][nt][1], u1 = ACC[0][nt][3],                             \
                  u2 = ACC[1][nt][1], u3 = ACC[1][nt][3];                             \
            ps[nt][1] = u0 + u1 + u2 + u3;                                            \
            pq[nt][1] = u0 * u0 + u1 * u1 + u2 * u2 + u3 * u3;                        \
        }                                                                             \
        _Pragma("unroll")                                                             \
        for (int o = 4; o <= 16; o <<= 1)                                             \
            _Pragma("unroll")                                                         \
            for (int nt = 0; nt < 4; nt++)                                            \
                _Pragma("unroll")                                                     \
                for (int pr = 0; pr < 2; pr++) {                                      \
                    ps[nt][pr] += __shfl_xor_sync(0xffffffffu, ps[nt][pr], o);        \
                    pq[nt][pr] += __shfl_xor_sync(0xffffffffu, pq[nt][pr], o);        \
                }                                                                     \
        if (lane < 4) {                                                               \
            _Pragma("unroll")                                                         \
            for (int nt = 0; nt < 4; nt++)                                            \
                _Pragma("unroll")                                                     \
                for (int pr = 0; pr < 2; pr++) {                                      \
                    SRED[warp][nt * 8 + 2 * lane + pr] = ps[nt][pr];                  \
                    SRED2[warp][nt * 8 + 2 * lane + pr] = pq[nt][pr];                 \
                }                                                                     \
        }                                                                             \
        __syncthreads();                                                              \
        if (tid < 64) {                                                               \
            int wn2 = tid >> 5, j2 = tid & 31;                                        \
            float ssum = 0.f, qsum = 0.f;                                             \
            _Pragma("unroll")                                                         \
            for (int wm2 = 0; wm2 < 4; wm2++) {                                       \
                ssum += SRED[wn2 * 4 + wm2][j2];                                      \
                qsum += SRED2[wn2 * 4 + wm2][j2];                                     \
            }                                                                         \
            g_pcs[(size_t)(SLOT) * 64 + wn2 * 32 + j2] = ssum;                        \
            g_pcs2[(size_t)(SLOT) * 64 + wn2 * 32 + j2] = qsum;                       \
        }                                                                             \
    }

// ---------------- FUSED features + enc1 GEMM ----------------
// CTA = 128 pixels. 4 slices of 64 ch; per slice build A/W/|A-W| chunks in smem
// and MMA against W1 chunks {s, 4+s, 8+s}. Tail chunk 12 = disp/conf/corr.
// As: [3][128][72] halves = 27648 halves. Bs: [3][64][72] = 13824. B12: [64][72] = 4608.
#define FUSED_SMEM ((27648 + 13824 + 4608) * 2)
__global__ void __launch_bounds__(256, 2) k_gemm1_fused(const float* __restrict__ cw,
                                                        const float* __restrict__ cf) {
    extern __shared__ __nv_bfloat16 dyn[];
    __nv_bfloat16* As = dyn;                 // 3 chunks
    __nv_bfloat16* Bs = dyn + 27648;         // 3 weight tiles
    __nv_bfloat16* B12 = dyn + 27648 + 13824;
    __shared__ float sred[8][32], sred2[8][32];
    int tid = threadIdx.x;
    int warp = tid >> 5, lane = tid & 31;
    int g = lane >> 2, t = lane & 3;
    int wm = warp & 3, wn = warp >> 2;

    int pix0 = blockIdx.x * 128;
    int prow = tid >> 1, h = tid & 1;        // pixel row + channel half
    int p = pix0 + prow;
    int b = p >> 14, hw = p & 16383;
    int py = hw >> 7, px = hw & 127;

    // prologue: B12 weight tile via cp.async
    {
        uint32_t b12a = smem_u32(B12);
#pragma unroll
        for (int i = 0; i < 2; i++) {
            int idx = tid + i * 256;
            int row = idx >> 3, seg = idx & 7;
            cp16(b12a + (uint32_t)(row * 72 + seg * 8) * 2,
                 g_w1k + 12 * 4096 + row * 64 + seg * 8);
        }
        cp_commit();
    }

    // grid math for own pixel
    float gx = clean15(cw[2 * p]);
    float gy = clean15(cw[2 * p + 1]);
    float xc = fmaf(gx, 64.f, 63.5f);
    float yc = fmaf(gy, 64.f, 63.5f);
    float x0f = floorf(xc), y0f = floorf(yc);
    float wx = xc - x0f, wy = yc - y0f;
    float iwx = 1.f - wx, iwy = 1.f - wy;
    int x0 = (int)x0f, y0 = (int)y0f;
    int off[4][4];
#pragma unroll
    for (int tt = 0; tt < 4; tt++) {
        int cyp = min(max(y0 - 1 + tt, 0), 127);
#pragma unroll
        for (int u = 0; u < 4; u++) {
            int cxp = min(max(x0 - 1 + u, 0), 127);
            off[tt][u] = (((b << 14) + (cyp << 7) + cxp) << 8);
        }
    }
    const __nv_bfloat16* farow = g_faT + ((size_t)((b << 14) | hw) << 8);
    uint32_t bs0 = smem_u32(Bs);

    float acc[2][4][4];
#pragma unroll
    for (int mt = 0; mt < 2; mt++)
#pragma unroll
        for (int nt = 0; nt < 4; nt++)
#pragma unroll
            for (int j = 0; j < 4; j++) acc[mt][nt][j] = 0.f;
    float na = 0.f, ns[9], dt[9];
#pragma unroll
    for (int s9 = 0; s9 < 9; s9++) { ns[s9] = 0.f; dt[s9] = 0.f; }

#pragma unroll 1
    for (int s = 0; s < 4; s++) {
        // issue this slice's 3 weight tiles (chunks s, 4+s, 8+s)
#pragma unroll
        for (int i = 0; i < 6; i++) {
            int idx = tid + i * 256;              // 0..1535
            int cc = idx >> 9, rem = idx & 511;
            int row = rem >> 3, seg = rem & 7;
            int chunk = (cc == 0) ? s : ((cc == 1) ? 4 + s : 8 + s);
            cp16(bs0 + (uint32_t)(cc * 4608 + row * 72 + seg * 8) * 2,
                 g_w1k + chunk * 4096 + row * 64 + seg * 8);
        }
        cp_commit();

        // build As: A slice, W slice, D slice (4 channels per inner step)
#pragma unroll 1
        for (int sub = 0; sub < 8; sub++) {
            int ch = s * 64 + h * 32 + sub * 4;
            uint2 faU = *(const uint2*)(farow + ch);
            float fav[4];
            {
                const __nv_bfloat162* hh = (const __nv_bfloat162*)&faU;
                float2 f0 = __bfloat1622float2(hh[0]);
                float2 f1 = __bfloat1622float2(hh[1]);
                fav[0] = f0.x; fav[1] = f0.y; fav[2] = f1.x; fav[3] = f1.y;
            }
            na += fav[0] * fav[0] + fav[1] * fav[1] + fav[2] * fav[2] + fav[3] * fav[3];

            float lxp[3][4], wv[4];
#pragma unroll
            for (int tt = 0; tt < 4; tt++) {
                float cv[4][4];
#pragma unroll
                for (int u = 0; u < 4; u++) {
                    uint2 U = *(const uint2*)(g_fbT + off[tt][u] + ch);
                    const __nv_bfloat162* hh = (const __nv_bfloat162*)&U;
                    float2 f0 = __bfloat1622float2(hh[0]);
                    float2 f1 = __bfloat1622float2(hh[1]);
                    cv[u][0] = f0.x; cv[u][1] = f0.y; cv[u][2] = f1.x; cv[u][3] = f1.y;
                }
                float lx[3][4];
#pragma unroll
                for (int j = 0; j < 4; j++) {
                    lx[0][j] = cv[0][j] * iwx + cv[1][j] * wx;
                    lx[1][j] = cv[1][j] * iwx + cv[2][j] * wx;
                    lx[2][j] = cv[2][j] * iwx + cv[3][j] * wx;
                }
                if (tt > 0) {
                    int dyrow = tt - 1;
#pragma unroll
                    for (int i = 0; i < 3; i++) {
                        int s9 = dyrow * 3 + i;
#pragma unroll
                        for (int j = 0; j < 4; j++) {
                            float v = lxp[i][j] * iwy + lx[i][j] * wy;
                            ns[s9] += v * v;
                            dt[s9] += fav[j] * v;
                            if (dyrow == 1 && i == 1) wv[j] = v;
                        }
                    }
                }
#pragma unroll
                for (int i = 0; i < 3; i++)
#pragma unroll
                    for (int j = 0; j < 4; j++) lxp[i][j] = lx[i][j];
            }
            int dstoff = prow * 72 + h * 32 + sub * 4;
            *(uint2*)(As + dstoff) = faU;
            uint2 W_, D_;
            {
                __nv_bfloat162* wh = (__nv_bfloat162*)&W_;
                __nv_bfloat162* dh = (__nv_bfloat162*)&D_;
                wh[0] = __floats2bfloat162_rn(wv[0], wv[1]);
                wh[1] = __floats2bfloat162_rn(wv[2], wv[3]);
                dh[0] = __floats2bfloat162_rn(fabsf(fav[0] - wv[0]), fabsf(fav[1] - wv[1]));
                dh[1] = __floats2bfloat162_rn(fabsf(fav[2] - wv[2]), fabsf(fav[3] - wv[3]));
            }
            *(uint2*)(As + 9216 + dstoff) = W_;
            *(uint2*)(As + 18432 + dstoff) = D_;
        }
        cp_wait<0>();
        __syncthreads();

        // MMA the 3 chunks
#pragma unroll 1
        for (int cc = 0; cc < 3; cc++) {
            const __nv_bfloat16* Ab = As + cc * 9216;
            const __nv_bfloat16* Bb = Bs + cc * 4608;
#pragma unroll
            for (int ks = 0; ks < 4; ks++) {
                int k0 = ks * 16;
                uint32_t a[2][4], bb[4][2];
#pragma unroll
                for (int mt = 0; mt < 2; mt++) {
                    int row0 = wm * 32 + mt * 16 + g;
                    a[mt][0] = *(const uint32_t*)(Ab + row0 * 72 + k0 + 2 * t);
                    a[mt][1] = *(const uint32_t*)(Ab + (row0 + 8) * 72 + k0 + 2 * t);
                    a[mt][2] = *(const uint32_t*)(Ab + row0 * 72 + k0 + 2 * t + 8);
                    a[mt][3] = *(const uint32_t*)(Ab + (row0 + 8) * 72 + k0 + 2 * t + 8);
                }
#pragma unroll
                for (int nt = 0; nt < 4; nt++) {
                    int n = wn * 32 + nt * 8 + g;
                    bb[nt][0] = *(const uint32_t*)(Bb + n * 72 + k0 + 2 * t);
                    bb[nt][1] = *(const uint32_t*)(Bb + n * 72 + k0 + 2 * t + 8);
                }
#pragma unroll
                for (int mt = 0; mt < 2; mt++)
#pragma unroll
                    for (int nt = 0; nt < 4; nt++)
                        mma16816(acc[mt][nt], a[mt], bb[nt]);
            }
        }
        __syncthreads();
    }

    // tail chunk 12: combine pair partials, build disp/conf/corr
    na += __shfl_xor_sync(0xffffffffu, na, 1);
#pragma unroll
    for (int s9 = 0; s9 < 9; s9++) {
        ns[s9] += __shfl_xor_sync(0xffffffffu, ns[s9], 1);
        dt[s9] += __shfl_xor_sync(0xffffffffu, dt[s9], 1);
    }
    {
        int dstoff = prow * 72 + h * 32;
#pragma unroll
        for (int j = 0; j < 32; j++) As[dstoff + j] = __float2bfloat16(0.f);
        if (h == 0) {
            float sna = fmaxf(sqrtf(na), 1e-12f);
            float dispx = gx - ((px + 0.5f) * (2.f / 128.f) - 1.f);
            float dispy = gy - ((py + 0.5f) * (2.f / 128.f) - 1.f);
            float cfv = cf[p];
            if (!(cfv == cfv)) cfv = 0.f;
            cfv = fminf(fmaxf(cfv, 0.f), 1.f);
            As[dstoff + 0] = __float2bfloat16(dispx);
            As[dstoff + 1] = __float2bfloat16(dispy);
            As[dstoff + 2] = __float2bfloat16(cfv);
#pragma unroll
            for (int s9 = 0; s9 < 9; s9++)
                As[dstoff + 3 + s9] =
                    __float2bfloat16(dt[s9] / (sna * fmaxf(sqrtf(ns[s9]), 1e-12f)));
        }
    }
    __syncthreads();
    {   // MMA chunk 12
        const __nv_bfloat16* Ab = As;
        const __nv_bfloat16* Bb = B12;
#pragma unroll
        for (int ks = 0; ks < 4; ks++) {
            int k0 = ks * 16;
            uint32_t a[2][4], bb[4][2];
#pragma unroll
            for (int mt = 0; mt < 2; mt++) {
                int row0 = wm * 32 + mt * 16 + g;
                a[mt][0] = *(const uint32_t*)(Ab + row0 * 72 + k0 + 2 * t);
                a[mt][1] = *(const uint32_t*)(Ab + (row0 + 8) * 72 + k0 + 2 * t);
                a[mt][2] = *(const uint32_t*)(Ab + row0 * 72 + k0 + 2 * t + 8);
                a[mt][3] = *(const uint32_t*)(Ab + (row0 + 8) * 72 + k0 + 2 * t + 8);
            }
#pragma unroll
            for (int nt = 0; nt < 4; nt++) {
                int n = wn * 32 + nt * 8 + g;
                bb[nt][0] = *(const uint32_t*)(Bb + n * 72 + k0 + 2 * t);
                bb[nt][1] = *(const uint32_t*)(Bb + n * 72 + k0 + 2 * t + 8);
            }
#pragma unroll
            for (int mt = 0; mt < 2; mt++)
#pragma unroll
                for (int nt = 0; nt < 4; nt++)
                    mma16816(acc[mt][nt], a[mt], bb[nt]);
        }
    }

    // epilogue: store h1 + stats partials
#pragma unroll
    for (int mt = 0; mt < 2; mt++) {
        int row = wm * 32 + mt * 16 + g;
#pragma unroll
        for (int nt = 0; nt < 4; nt++) {
            int col = wn * 32 + nt * 8 + 2 * t;
            float* dst = g_h1 + (size_t)(pix0 + row) * 64 + col;
            *(float2*)dst = make_float2(acc[mt][nt][0], acc[mt][nt][1]);
            *(float2*)(dst + 512) = make_float2(acc[mt][nt][2], acc[mt][nt][3]);
        }
    }
    __syncthreads();
    STATS_EPILOGUE(acc, sred, sred2, blockIdx.x)
}

// ---------------- 3x3 conv: cp.async weights overlapped with GELU halo ----------------
#define CONV_SMEM (180 * 72 * 2 + 9 * 64 * 72 * 2)
__global__ void __launch_bounds__(256) k_conv_mma(int which, int srcsel) {
    extern __shared__ __nv_bfloat16 sm[];
    __nv_bfloat16* halo = sm;                 // [pix 180][72]
    __nv_bfloat16* Bs = sm + 180 * 72;        // [tap 9][64][72]
    __shared__ float sg[64], st[64];
    __shared__ float sred[8][32], sred2[8][32];
    const float* src = srcsel ? g_h2 : g_h1;
    float* dst = srcsel ? g_h1 : g_h2;
    int tid = threadIdx.x;
    int warp = tid >> 5, lane = tid & 31;
    int g = lane >> 2, t = lane & 3;
    int wm = warp & 3, wn = warp >> 2;
    int b = blockIdx.x >> 7;
    int tile = blockIdx.x & 127;
    int y0 = (tile >> 4) * 16, x0 = (tile & 15) * 8;

    {
        uint32_t bs0 = smem_u32(Bs);
#pragma unroll
        for (int i = 0; i < 18; i++) {
            int idx = tid + i * 256;
            int tap = idx >> 9, rem = idx & 511;
            int row = rem >> 3, seg = rem & 7;
            cp16(bs0 + (tap * 4608 + row * 72 + seg * 8) * 2,
                 g_wck[which] + tap * 4096 + row * 64 + seg * 8);
        }
        cp_commit();
    }

    if (tid < 64) { sg[tid] = g_gns[b * 64 + tid]; st[tid] = g_gnt[b * 64 + tid]; }
    __syncthreads();

    for (int idx = tid; idx < 1440; idx += 256) {
        int pix = idx >> 3, seg = idx & 7;
        int yy = pix / 10, xx = pix - yy * 10;
        int gy = y0 + yy - 1, gx = x0 + xx - 1;
        uint4 v = make_uint4(0, 0, 0, 0);
        if (gy >= 0 && gy < 128 && gx >= 0 && gx < 128) {
            const float4* sp = (const float4*)(src + (size_t)((b << 14) + (gy << 7) + gx) * 64 + seg * 8);
            float4 r0 = sp[0], r1 = sp[1];
            int cb = seg * 8;
            float o0 = geluf(fmaf(r0.x, sg[cb], st[cb]));
            float o1 = geluf(fmaf(r0.y, sg[cb + 1], st[cb + 1]));
            float o2 = geluf(fmaf(r0.z, sg[cb + 2], st[cb + 2]));
            float o3 = geluf(fmaf(r0.w, sg[cb + 3], st[cb + 3]));
            float o4 = geluf(fmaf(r1.x, sg[cb + 4], st[cb + 4]));
            float o5 = geluf(fmaf(r1.y, sg[cb + 5], st[cb + 5]));
            float o6 = geluf(fmaf(r1.z, sg[cb + 6], st[cb + 6]));
            float o7 = geluf(fmaf(r1.w, sg[cb + 7], st[cb + 7]));
            __nv_bfloat162* vh = (__nv_bfloat162*)&v;
            vh[0] = __floats2bfloat162_rn(o0, o1);
            vh[1] = __floats2bfloat162_rn(o2, o3);
            vh[2] = __floats2bfloat162_rn(o4, o5);
            vh[3] = __floats2bfloat162_rn(o6, o7);
        }
        *(uint4*)(halo + pix * 72 + seg * 8) = v;
    }
    cp_wait<0>();
    __syncthreads();

    float acc[2][4][4];
#pragma unroll
    for (int mt = 0; mt < 2; mt++)
#pragma unroll
        for (int nt = 0; nt < 4; nt++)
#pragma unroll
            for (int j = 0; j < 4; j++) acc[mt][nt][j] = 0.f;

#pragma unroll 1
    for (int tap = 0; tap < 9; tap++) {
        int dy = tap / 3 - 1, dx = tap % 3 - 1;
        const __nv_bfloat16* Bt = Bs + tap * 4608;
#pragma unroll
        for (int ks = 0; ks < 4; ks++) {
            int k0 = ks * 16;
            uint32_t a[2][4], bb[4][2];
#pragma unroll
            for (int mt = 0; mt < 2; mt++) {
                int ry = wm * 4 + mt * 2;
                int p0 = (ry + 1 + dy) * 10 + (g + 1 + dx);
                int p1 = p0 + 10;
                a[mt][0] = *(const uint32_t*)(halo + p0 * 72 + k0 + 2 * t);
                a[mt][1] = *(const uint32_t*)(halo + p1 * 72 + k0 + 2 * t);
                a[mt][2] = *(const uint32_t*)(halo + p0 * 72 + k0 + 2 * t + 8);
                a[mt][3] = *(const uint32_t*)(halo + p1 * 72 + k0 + 2 * t + 8);
            }
#pragma unroll
            for (int nt = 0; nt < 4; nt++) {
                int n = wn * 32 + nt * 8 + g;
                bb[nt][0] = *(const uint32_t*)(Bt + n * 72 + k0 + 2 * t);
                bb[nt][1] = *(const uint32_t*)(Bt + n * 72 + k0 + 2 * t + 8);
            }
#pragma unroll
            for (int mt = 0; mt < 2; mt++)
#pragma unroll
                for (int nt = 0; nt < 4; nt++)
                    mma16816(acc[mt][nt], a[mt], bb[nt]);
        }
    }
#pragma unroll
    for (int mt = 0; mt < 2; mt++) {
        int row = wm * 32 + mt * 16 + g;
        int py = y0 + (row >> 3), px = x0 + (row & 7);
#pragma unroll
        for (int nt = 0; nt < 4; nt++) {
            int col = wn * 32 + nt * 8 + 2 * t;
            float* d1 = dst + (size_t)((b << 14) + (py << 7) + px) * 64 + col;
            *(float2*)d1 = make_float2(acc[mt][nt][0], acc[mt][nt][1]);
            float* d2 = dst + (size_t)((b << 14) + ((py + 1) << 7) + px) * 64 + col;
            *(float2*)d2 = make_float2(acc[mt][nt][2], acc[mt][nt][3]);
        }
    }
    __syncthreads();
    STATS_EPILOGUE(acc, sred, sred2, blockIdx.x)
}

// ---------------- GN stats stage 2 ----------------
__global__ void k_stats2(const float* __restrict__ gam, const float* __restrict__ bet) {
    int b = blockIdx.x;
    int tid = threadIdx.x;            // 512
    int c = tid & 63, sl = tid >> 6;
    float s = 0.f, s2 = 0.f;
    int base = b * 128 + sl * 16;
#pragma unroll 4
    for (int i = 0; i < 16; i++) {
        s += g_pcs[(size_t)(base + i) * 64 + c];
        s2 += g_pcs2[(size_t)(base + i) * 64 + c];
    }
    __shared__ float ss[8][64], qq[8][64];
    __shared__ float cs[64], cq[64];
    ss[sl][c] = s; qq[sl][c] = s2;
    __syncthreads();
    if (sl == 0) {
        float S = 0.f, Q = 0.f;
#pragma unroll
        for (int j = 0; j < 8; j++) { S += ss[j][c]; Q += qq[j][c]; }
        cs[c] = S; cq[c] = Q;
    }
    __syncthreads();
    if (sl == 0) {
        float gs = 0.f, gq = 0.f;
        int gb = c & ~7;
#pragma unroll
        for (int j = 0; j < 8; j++) { gs += cs[gb + j]; gq += cq[gb + j]; }
        float mu = gs * (1.f / 131072.f);
        float var = gq * (1.f / 131072.f) - mu * mu;
        float sc = gam[c] * rsqrtf(var + 1e-5f);
        g_gns[b * 64 + c] = sc;
        g_gnt[b * 64 + c] = bet[c] - mu * sc;
    }
}

// ---------------- heads ----------------
__global__ void __launch_bounds__(256) k_heads(const float* __restrict__ dw, const float* __restrict__ db,
                                               const float* __restrict__ cwt, const float* __restrict__ cb,
                                               const float* __restrict__ warp, const float* __restrict__ conf,
                                               float* __restrict__ out) {
    __shared__ float sw[3 * 9 * 64];
    int tid = threadIdx.x;
    for (int idx = tid; idx < 1728; idx += 256) {
        int o = idx / 576, rem = idx - o * 576;
        int tap = rem >> 6, c = rem & 63;
        sw[idx] = (o < 2) ? dw[(o * 64 + c) * 9 + tap] : cwt[c * 9 + tap];
    }
    __syncthreads();
    int wr = tid >> 5, lane = tid & 31;
    int p0 = (blockIdx.x * 8 + wr) * 4;
    int b = p0 >> 14, hw = p0 & 16383;
    int y = hw >> 7, x0 = hw & 127;
    int c2 = lane * 2;
    float s0 = g_gns[b * 64 + c2], s1 = g_gns[b * 64 + c2 + 1];
    float t0 = g_gnt[b * 64 + c2], t1 = g_gnt[b * 64 + c2 + 1];

    float nb[3][6][2];
#pragma unroll
    for (int ry = 0; ry < 3; ry++) {
        int yy = y - 1 + ry;
#pragma unroll
        for (int cx = 0; cx < 6; cx++) {
            int xx = x0 - 1 + cx;
            float v0 = 0.f, v1 = 0.f;
            if (yy >= 0 && yy < 128 && xx >= 0 && xx < 128) {
                float2 h = *(const float2*)(g_h1 + (size_t)((b << 14) + (yy << 7) + xx) * 64 + c2);
                v0 = geluf(fmaf(h.x, s0, t0));
                v1 = geluf(fmaf(h.y, s1, t1));
            }
            nb[ry][cx][0] = v0; nb[ry][cx][1] = v1;
        }
    }
    float acc[4][3];
#pragma unroll
    for (int j = 0; j < 4; j++)
#pragma unroll
        for (int o = 0; o < 3; o++) acc[j][o] = 0.f;
#pragma unroll
    for (int ky = 0; ky < 3; ky++)
#pragma unroll
        for (int kx = 0; kx < 3; kx++) {
            int tap = ky * 3 + kx;
            float w0a = sw[tap * 64 + c2], w0b = sw[tap * 64 + c2 + 1];
            float w1a = sw[576 + tap * 64 + c2], w1b = sw[576 + tap * 64 + c2 + 1];
            float w2a = sw[1152 + tap * 64 + c2], w2b = sw[1152 + tap * 64 + c2 + 1];
#pragma unroll
            for (int j = 0; j < 4; j++) {
                float v0 = nb[ky][j + kx][0], v1 = nb[ky][j + kx][1];
                acc[j][0] += w0a * v0 + w0b * v1;
                acc[j][1] += w1a * v0 + w1b * v1;
                acc[j][2] += w2a * v0 + w2b * v1;
            }
        }
#pragma unroll
    for (int o = 16; o; o >>= 1)
#pragma unroll
        for (int j = 0; j < 4; j++) {
            acc[j][0] += __shfl_xor_sync(0xffffffffu, acc[j][0], o);
            acc[j][1] += __shfl_xor_sync(0xffffffffu, acc[j][1], o);
            acc[j][2] += __shfl_xor_sync(0xffffffffu, acc[j][2], o);
        }
    if (lane < 4) {
        int p = p0 + lane;
        float a0 = acc[lane][0], a1 = acc[lane][1], a2 = acc[lane][2];
        float rx = clean15(warp[2 * p]);
        float ry = clean15(warp[2 * p + 1]);
        float fwx = fminf(fmaxf(rx + tanhf(a0 + db[0]) * 0.0625f, -1.5f), 1.5f);
        float fwy = fminf(fmaxf(ry + tanhf(a1 + db[1]) * 0.0625f, -1.5f), 1.5f);
        float cv = conf[p];
        if (!(cv == cv)) cv = 0.f;
        cv = fminf(fmaxf(cv, 0.f), 1.f);
        float pp = fminf(fmaxf(cv, 1e-4f), 1.f - 1e-4f);
        float base = logf(pp) - log1pf(-pp);
        float lg = base + 0.5f * (a2 + cb[0]);
        float rc = fminf(fmaxf(1.f / (1.f + expf(-lg)), 0.f), 1.f);
        out[2 * p] = fwx;
        out[2 * p + 1] = fwy;
        out[65536 + p] = rc;
        out[98304 + p] = lg;
    }
}

extern "C" void kernel_launch(void* const* d_in, const int* in_sizes, int n_in,
                              void* d_out, int out_size) {
    (void)in_sizes; (void)n_in; (void)out_size;
    const float* fA  = (const float*)d_in[0];
    const float* fB  = (const float*)d_in[1];
    const float* cw  = (const float*)d_in[2];
    const float* cf  = (const float*)d_in[3];
    const float* e1w = (const float*)d_in[4];
    const float* g1g = (const float*)d_in[5];
    const float* g1b = (const float*)d_in[6];
    const float* e2w = (const float*)d_in[7];
    const float* g2g = (const float*)d_in[8];
    const float* g2b = (const float*)d_in[9];
    const float* e3w = (const float*)d_in[10];
    const float* g3g = (const float*)d_in[11];
    const float* g3b = (const float*)d_in[12];
    const float* dw  = (const float*)d_in[13];
    const float* db  = (const float*)d_in[14];
    const float* cwt = (const float*)d_in[15];
    const float* cb  = (const float*)d_in[16];
    float* out = (float*)d_out;

    cudaFuncSetAttribute(k_gemm1_fused, cudaFuncAttributeMaxDynamicSharedMemorySize, FUSED_SMEM);
    cudaFuncSetAttribute(k_conv_mma, cudaFuncAttributeMaxDynamicSharedMemorySize, CONV_SMEM);

    k_transpose<<<dim3(512, 4, 4), dim3(32, 8)>>>(fA, fB);
    k_wprep<<<496, 256>>>(e1w, e2w, e3w);
    k_gemm1_fused<<<256, 256, FUSED_SMEM>>>(cw, cf);
    k_stats2<<<2, 512>>>(g1g, g1b);
    k_conv_mma<<<256, 256, CONV_SMEM>>>(0, 0);   // read g_h1 -> g_h2
    k_stats2<<<2, 512>>>(g2g, g2b);
    k_conv_mma<<<256, 256, CONV_SMEM>>>(1, 1);   // read g_h2 -> g_h1
    k_stats2<<<2, 512>>>(g3g, g3b);
    k_heads<<<1024, 256>>>(dw, db, cwt, cb, cw, cf, out);
}

// round 10
// speedup vs baseline: 1.1848x; 1.1848x over previous
#include <cuda_runtime.h>
#include <cuda_bf16.h>
#include <math.h>
#include <stdint.h>

#define HWSZ 16384
#define NPIX 32768
#define CC 256

// ---------------- static device scratch ----------------
__device__ __align__(16) __nv_bfloat16 g_fbT[2 * HWSZ * CC];     // feat_B NHWC bf16
__device__ __align__(16) __nv_bfloat16 g_xb[(size_t)NPIX * 832]; // X features bf16 (780 pad->832)
__device__ __align__(16) __nv_bfloat16 g_w1k[13 * 4096];         // enc1 W [chunk][oc][k64]
__device__ __align__(16) __nv_bfloat16 g_wck[2][9 * 4096];       // conv W [tap][oc][ci]
__device__ __align__(16) float g_h1[(size_t)NPIX * 64];          // raw layer out ping
__device__ __align__(16) float g_h2[(size_t)NPIX * 64];          // raw layer out pong
__device__ float g_gns[128];
__device__ float g_gnt[128];
__device__ float g_pcs[256 * 64];
__device__ float g_pcs2[256 * 64];
__device__ int g_ctr;   // zero-init; reset by last CTA after each use

__device__ __forceinline__ float clean15(float v) {
    if (!(v == v)) return 0.f;
    return fminf(fmaxf(v, -1.5f), 1.5f);
}
__device__ __forceinline__ float geluf(float z) {
    return 0.5f * z * (1.f + erff(z * 0.70710678118654752f));
}
__device__ __forceinline__ uint32_t smem_u32(const void* p) {
    uint32_t r;
    asm("{ .reg .u64 t; cvta.to.shared.u64 t, %1; cvt.u32.u64 %0, t; }" : "=r"(r) : "l"(p));
    return r;
}
__device__ __forceinline__ void cp16(uint32_t dst, const void* src) {
    asm volatile("cp.async.cg.shared.global [%0], [%1], 16;" :: "r"(dst), "l"(src));
}
__device__ __forceinline__ void cp_commit() {
    asm volatile("cp.async.commit_group;" ::: "memory");
}
template <int N>
__device__ __forceinline__ void cp_wait() {
    asm volatile("cp.async.wait_group %0;" :: "n"(N) : "memory");
}

// bf16 HMMA: D(16x8,f32) += A(16x16,bf16) * B(8x16,bf16)^T
__device__ __forceinline__ void mma16816(float* d, const uint32_t* a, const uint32_t* b) {
    asm volatile(
        "mma.sync.aligned.m16n8k16.row.col.f32.bf16.bf16.f32 "
        "{%0,%1,%2,%3}, {%4,%5,%6,%7}, {%8,%9}, {%0,%1,%2,%3};"
        : "+f"(d[0]), "+f"(d[1]), "+f"(d[2]), "+f"(d[3])
        : "r"(a[0]), "r"(a[1]), "r"(a[2]), "r"(a[3]), "r"(b[0]), "r"(b[1]));
}

// ---------------- K0: NCHW fp32 -> bf16 transpose ----------------
__global__ void k_transpose(const float* __restrict__ fA, const float* __restrict__ fB) {
    __shared__ float tile[64][33];
    int z = blockIdx.z;
    const float* src = (z >= 2) ? fB : fA;
    int b = z & 1;
    src += (size_t)b * CC * HWSZ;
    __nv_bfloat16* dstbase;
    size_t stride;
    if (z < 2) { dstbase = g_xb + (size_t)(b << 14) * 832; stride = 832; }
    else       { dstbase = g_fbT + ((size_t)(b << 14) << 8); stride = 256; }
    int hw0 = blockIdx.x * 32, c0 = blockIdx.y * 64;
    int tx = threadIdx.x, ty = threadIdx.y;          // (32,8)
#pragma unroll
    for (int i = 0; i < 8; i++) {
        int cr = ty + i * 8;
        tile[cr][tx] = src[(c0 + cr) * HWSZ + hw0 + tx];
    }
    __syncthreads();
#pragma unroll
    for (int i = 0; i < 4; i++) {
        int r = ty + i * 8;
        __nv_bfloat162 v = __floats2bfloat162_rn(tile[2 * tx][r], tile[2 * tx + 1][r]);
        *(__nv_bfloat162*)(dstbase + (size_t)(hw0 + r) * stride + c0 + 2 * tx) = v;
    }
}

// ---------------- weight prep ----------------
__global__ void k_wprep(const float* __restrict__ w1, const float* __restrict__ w2,
                        const float* __restrict__ w3) {
    int blk = blockIdx.x;
    if (blk < 208) {
        int idx = blk * 256 + threadIdx.x;
        if (idx >= 13 * 4096) return;
        int chunk = idx >> 12, rem = idx & 4095;
        int oc = rem >> 6, k = rem & 63;
        int kg = chunk * 64 + k;
        g_w1k[idx] = __float2bfloat16((kg < 780) ? w1[oc * 780 + kg] : 0.f);
    } else {
        int which = (blk < 352) ? 0 : 1;
        const float* w = which ? w3 : w2;
        int idx = (blk - (which ? 352 : 208)) * 256 + threadIdx.x;
        if (idx >= 9 * 4096) return;
        int tap = idx >> 12, rem = idx & 4095;
        int oc = rem >> 6, ci = rem & 63;
        g_wck[which][idx] = __float2bfloat16(w[(oc * 64 + ci) * 9 + tap]);
    }
}

// ---------------- K1: per-pixel features ----------------
__global__ void __launch_bounds__(256) k_features(const float* __restrict__ cw,
                                                  const float* __restrict__ cf) {
    int p = blockIdx.x * 8 + (threadIdx.x >> 5);
    int lane = threadIdx.x & 31;
    int b = p >> 14, hw = p & 16383;
    int py = hw >> 7, px = hw & 127;

    float gx = clean15(cw[2 * p]);
    float gy = clean15(cw[2 * p + 1]);
    float xc = fmaf(gx, 64.f, 63.5f);
    float yc = fmaf(gy, 64.f, 63.5f);
    float x0f = floorf(xc), y0f = floorf(yc);
    float wx = xc - x0f, wy = yc - y0f;
    float iwx = 1.f - wx, iwy = 1.f - wy;
    int x0 = (int)x0f, y0 = (int)y0f;

    __nv_bfloat16* xrow = g_xb + (size_t)p * 832;
    int c = lane * 8;

    uint4 cU[4][4];
#pragma unroll
    for (int t = 0; t < 4; t++) {
        int cyp = min(max(y0 - 1 + t, 0), 127);
#pragma unroll
        for (int u = 0; u < 4; u++) {
            int cxp = min(max(x0 - 1 + u, 0), 127);
            cU[t][u] = *(const uint4*)(g_fbT + ((((b << 14) + (cyp << 7) + cxp) << 8) + c));
        }
    }
    uint4 faU = *(const uint4*)(xrow + c);

    float fav[8];
    {
        const __nv_bfloat162* h = (const __nv_bfloat162*)&faU;
#pragma unroll
        for (int j = 0; j < 4; j++) {
            float2 f = __bfloat1622float2(h[j]);
            fav[2 * j] = f.x; fav[2 * j + 1] = f.y;
        }
    }
    float na = 0.f, ns[9], dt[9];
#pragma unroll
    for (int s = 0; s < 9; s++) { ns[s] = 0.f; dt[s] = 0.f; }
#pragma unroll
    for (int j = 0; j < 8; j++) na += fav[j] * fav[j];

    float lxp[3][8];
    float wv[8];
#pragma unroll
    for (int t = 0; t < 4; t++) {
        float cv[4][8];
#pragma unroll
        for (int u = 0; u < 4; u++) {
            const __nv_bfloat162* h = (const __nv_bfloat162*)&cU[t][u];
#pragma unroll
            for (int j = 0; j < 4; j++) {
                float2 f = __bfloat1622float2(h[j]);
                cv[u][2 * j] = f.x; cv[u][2 * j + 1] = f.y;
            }
        }
        float lx[3][8];
#pragma unroll
        for (int j = 0; j < 8; j++) {
            lx[0][j] = cv[0][j] * iwx + cv[1][j] * wx;
            lx[1][j] = cv[1][j] * iwx + cv[2][j] * wx;
            lx[2][j] = cv[2][j] * iwx + cv[3][j] * wx;
        }
        if (t > 0) {
            int dyrow = t - 1;
#pragma unroll
            for (int i = 0; i < 3; i++) {
                int s = dyrow * 3 + i;
#pragma unroll
                for (int j = 0; j < 8; j++) {
                    float v = lxp[i][j] * iwy + lx[i][j] * wy;
                    ns[s] += v * v;
                    dt[s] += fav[j] * v;
                    if (dyrow == 1 && i == 1) wv[j] = v;
                }
            }
        }
#pragma unroll
        for (int i = 0; i < 3; i++)
#pragma unroll
            for (int j = 0; j < 8; j++) lxp[i][j] = lx[i][j];
    }
    {
        uint4 W, D;
        __nv_bfloat162* wh = (__nv_bfloat162*)&W;
        __nv_bfloat162* dh = (__nv_bfloat162*)&D;
#pragma unroll
        for (int j = 0; j < 4; j++) {
            wh[j] = __floats2bfloat162_rn(wv[2 * j], wv[2 * j + 1]);
            dh[j] = __floats2bfloat162_rn(fabsf(fav[2 * j] - wv[2 * j]),
                                          fabsf(fav[2 * j + 1] - wv[2 * j + 1]));
        }
        *(uint4*)(xrow + 256 + c) = W;
        *(uint4*)(xrow + 512 + c) = D;
    }

#pragma unroll
    for (int o = 16; o; o >>= 1) {
        na += __shfl_xor_sync(0xffffffffu, na, o);
#pragma unroll
        for (int s = 0; s < 9; s++) {
            ns[s] += __shfl_xor_sync(0xffffffffu, ns[s], o);
            dt[s] += __shfl_xor_sync(0xffffffffu, dt[s], o);
        }
    }
    if (lane == 0) {
        float sna = fmaxf(sqrtf(na), 1e-12f);
        float dispx = gx - ((px + 0.5f) * (2.f / 128.f) - 1.f);
        float dispy = gy - ((py + 0.5f) * (2.f / 128.f) - 1.f);
        float cfv = cf[p];
        if (!(cfv == cfv)) cfv = 0.f;
        cfv = fminf(fmaxf(cfv, 0.f), 1.f);
        xrow[768] = __float2bfloat16(dispx);
        xrow[769] = __float2bfloat16(dispy);
        xrow[770] = __float2bfloat16(cfv);
#pragma unroll
        for (int s = 0; s < 9; s++)
            xrow[771 + s] = __float2bfloat16(dt[s] / (sna * fmaxf(sqrtf(ns[s]), 1e-12f)));
    } else if (lane <= 13) {
        ((uint2*)(xrow + 780))[lane - 1] = make_uint2(0u, 0u);
    }
}

// ---------------- stats epilogue: per-CTA partials, then last-CTA GN finalize ----------------
#define STATS_EPILOGUE(ACC, SRED, SRED2, SLOT)                                        \
    {                                                                                 \
        float ps[4][2], pq[4][2];                                                     \
        _Pragma("unroll")                                                             \
        for (int nt = 0; nt < 4; nt++) {                                              \
            float v0 = ACC[0][nt][0], v1 = ACC[0][nt][2],                             \
                  v2 = ACC[1][nt][0], v3 = ACC[1][nt][2];                             \
            ps[nt][0] = v0 + v1 + v2 + v3;                                            \
            pq[nt][0] = v0 * v0 + v1 * v1 + v2 * v2 + v3 * v3;                        \
            float u0 = ACC[0][nt][1], u1 = ACC[0][nt][3],                             \
                  u2 = ACC[1][nt][1], u3 = ACC[1][nt][3];                             \
            ps[nt][1] = u0 + u1 + u2 + u3;                                            \
            pq[nt][1] = u0 * u0 + u1 * u1 + u2 * u2 + u3 * u3;                        \
        }                                                                             \
        _Pragma("unroll")                                                             \
        for (int o = 4; o <= 16; o <<= 1)                                             \
            _Pragma("unroll")                                                         \
            for (int nt = 0; nt < 4; nt++)                                            \
                _Pragma("unroll")                                                     \
                for (int pr = 0; pr < 2; pr++) {                                      \
                    ps[nt][pr] += __shfl_xor_sync(0xffffffffu, ps[nt][pr], o);        \
                    pq[nt][pr] += __shfl_xor_sync(0xffffffffu, pq[nt][pr], o);        \
                }                                                                     \
        if (lane < 4) {                                                               \
            _Pragma("unroll")                                                         \
            for (int nt = 0; nt < 4; nt++)                                            \
                _Pragma("unroll")                                                     \
                for (int pr = 0; pr < 2; pr++) {                                      \
                    SRED[warp][nt * 8 + 2 * lane + pr] = ps[nt][pr];                  \
                    SRED2[warp][nt * 8 + 2 * lane + pr] = pq[nt][pr];                 \
                }                                                                     \
        }                                                                             \
        __syncthreads();                                                              \
        if (tid < 64) {                                                               \
            int wn2 = tid >> 5, j2 = tid & 31;                                        \
            float ssum = 0.f, qsum = 0.f;                                             \
            _Pragma("unroll")                                                         \
            for (int wm2 = 0; wm2 < 4; wm2++) {                                       \
                ssum += SRED[wn2 * 4 + wm2][j2];                                      \
                qsum += SRED2[wn2 * 4 + wm2][j2];                                     \
            }                                                                         \
            g_pcs[(size_t)(SLOT) * 64 + wn2 * 32 + j2] = ssum;                        \
            g_pcs2[(size_t)(SLOT) * 64 + wn2 * 32 + j2] = qsum;                       \
            __threadfence();                                                          \
        }                                                                             \
        __syncthreads();                                                              \
    }

// last-CTA GN finalize: fold 128 slots per batch -> g_gns/g_gnt. Deterministic
// (fixed summation order, executed once by whichever CTA finishes last).
__device__ __forceinline__ void gn_finalize(int tid, const float* gam, const float* bet) {
    __shared__ int s_last;
    if (tid == 0) {
        int old = atomicAdd(&g_ctr, 1);
        s_last = (old == 255) ? 1 : 0;
    }
    __syncthreads();
    if (!s_last) return;
    __threadfence();
    int pr = tid & 127;              // (b,c) pair: b = pr>>6, c = pr&63
    int half = tid >> 7;             // 0/1: slots [0,64) / [64,128) within batch
    int bb2 = pr >> 6, c = pr & 63;
    int base = bb2 * 128 + half * 64;
    float s = 0.f, q = 0.f;
#pragma unroll 4
    for (int i = 0; i < 64; i++) {
        s += g_pcs[(size_t)(base + i) * 64 + c];
        q += g_pcs2[(size_t)(base + i) * 64 + c];
    }
    __shared__ float fs[2][128], fq[2][128];
    fs[half][pr] = s; fq[half][pr] = q;
    __syncthreads();
    if (half == 0) {
        fs[0][pr] = fs[0][pr] + fs[1][pr];
        fq[0][pr] = fq[0][pr] + fq[1][pr];
    }
    __syncthreads();
    if (half == 0) {
        int gb = pr & ~7;
        float gs = 0.f, gq = 0.f;
#pragma unroll
        for (int j = 0; j < 8; j++) { gs += fs[0][gb + j]; gq += fq[0][gb + j]; }
        float mu = gs * (1.f / 131072.f);
        float var = gq * (1.f / 131072.f) - mu * mu;
        float sc = gam[c] * rsqrtf(var + 1e-5f);
        g_gns[pr] = sc;
        g_gnt[pr] = bet[c] - mu * sc;
    }
    if (tid == 0) g_ctr = 0;
    __threadfence();
}

// ---------------- enc1 GEMM: 4-stage cp.async pipeline + GN finalize ----------------
#define GEMM_SMEM (4 * 9216 * 2 + 4 * 4608 * 2)
__global__ void __launch_bounds__(256) k_gemm1_mma(const float* __restrict__ gam,
                                                   const float* __restrict__ bet) {
    extern __shared__ __nv_bfloat16 dyn[];
    __nv_bfloat16* As = dyn;               // [4][128*72]
    __nv_bfloat16* Bs = dyn + 4 * 9216;    // [4][64*72]
    __shared__ float sred[8][32], sred2[8][32];
    int tid = threadIdx.x;
    int warp = tid >> 5, lane = tid & 31;
    int g = lane >> 2, t = lane & 3;
    int wm = warp & 3, wn = warp >> 2;
    float acc[2][4][4];
#pragma unroll
    for (int mt = 0; mt < 2; mt++)
#pragma unroll
        for (int nt = 0; nt < 4; nt++)
#pragma unroll
            for (int j = 0; j < 4; j++) acc[mt][nt][j] = 0.f;

    int pix0 = blockIdx.x * 128;
    int arow = tid >> 1, acol = (tid & 1) * 32;
    const __nv_bfloat16* asrc0 = g_xb + (size_t)(pix0 + arow) * 832 + acol;
    uint32_t adst0 = smem_u32(As + arow * 72 + acol);
    int brow0 = tid >> 3, bseg = (tid & 7) * 8;
    uint32_t bdst0 = smem_u32(Bs + brow0 * 72 + bseg);
    const __nv_bfloat16* bsrc0 = g_w1k + brow0 * 64 + bseg;

    auto load_chunk = [&](int chunk) {
        int buf = chunk & 3;
        uint32_t ad = adst0 + buf * 9216 * 2;
        const __nv_bfloat16* as = asrc0 + chunk * 64;
#pragma unroll
        for (int j = 0; j < 4; j++)
            cp16(ad + j * 16, as + j * 8);
        uint32_t bd = bdst0 + buf * 4608 * 2;
        const __nv_bfloat16* bs = bsrc0 + chunk * 4096;
        cp16(bd, bs);
        cp16(bd + 32 * 72 * 2, bs + 32 * 64);
    };

    load_chunk(0); cp_commit();
    load_chunk(1); cp_commit();
    load_chunk(2); cp_commit();
    for (int chunk = 0; chunk < 13; chunk++) {
        if (chunk + 3 < 13) load_chunk(chunk + 3);
        cp_commit();
        cp_wait<3>();
        __syncthreads();
        int buf = chunk & 3;
        const __nv_bfloat16* Ab = As + buf * 9216;
        const __nv_bfloat16* Bb = Bs + buf * 4608;
#pragma unroll
        for (int ks = 0; ks < 4; ks++) {
            int k0 = ks * 16;
            uint32_t a[2][4], bb[4][2];
#pragma unroll
            for (int mt = 0; mt < 2; mt++) {
                int row0 = wm * 32 + mt * 16 + g;
                a[mt][0] = *(const uint32_t*)(Ab + row0 * 72 + k0 + 2 * t);
                a[mt][1] = *(const uint32_t*)(Ab + (row0 + 8) * 72 + k0 + 2 * t);
                a[mt][2] = *(const uint32_t*)(Ab + row0 * 72 + k0 + 2 * t + 8);
                a[mt][3] = *(const uint32_t*)(Ab + (row0 + 8) * 72 + k0 + 2 * t + 8);
            }
#pragma unroll
            for (int nt = 0; nt < 4; nt++) {
                int n = wn * 32 + nt * 8 + g;
                bb[nt][0] = *(const uint32_t*)(Bb + n * 72 + k0 + 2 * t);
                bb[nt][1] = *(const uint32_t*)(Bb + n * 72 + k0 + 2 * t + 8);
            }
#pragma unroll
            for (int mt = 0; mt < 2; mt++)
#pragma unroll
                for (int nt = 0; nt < 4; nt++)
                    mma16816(acc[mt][nt], a[mt], bb[nt]);
        }
        __syncthreads();
    }
#pragma unroll
    for (int mt = 0; mt < 2; mt++) {
        int row = wm * 32 + mt * 16 + g;
#pragma unroll
        for (int nt = 0; nt < 4; nt++) {
            int col = wn * 32 + nt * 8 + 2 * t;
            float* dst = g_h1 + (size_t)(pix0 + row) * 64 + col;
            *(float2*)dst = make_float2(acc[mt][nt][0], acc[mt][nt][1]);
            *(float2*)(dst + 512) = make_float2(acc[mt][nt][2], acc[mt][nt][3]);
        }
    }
    __syncthreads();
    STATS_EPILOGUE(acc, sred, sred2, blockIdx.x)
    gn_finalize(tid, gam, bet);
}

// ---------------- 3x3 conv + GN finalize ----------------
#define CONV_SMEM (180 * 72 * 2 + 9 * 64 * 72 * 2)
__global__ void __launch_bounds__(256) k_conv_mma(int which, int srcsel,
                                                  const float* __restrict__ gam,
                                                  const float* __restrict__ bet) {
    extern __shared__ __nv_bfloat16 sm[];
    __nv_bfloat16* halo = sm;                 // [pix 180][72]
    __nv_bfloat16* Bs = sm + 180 * 72;        // [tap 9][64][72]
    __shared__ float sg[64], st[64];
    __shared__ float sred[8][32], sred2[8][32];
    const float* src = srcsel ? g_h2 : g_h1;
    float* dst = srcsel ? g_h1 : g_h2;
    int tid = threadIdx.x;
    int warp = tid >> 5, lane = tid & 31;
    int g = lane >> 2, t = lane & 3;
    int wm = warp & 3, wn = warp >> 2;
    int b = blockIdx.x >> 7;
    int tile = blockIdx.x & 127;
    int y0 = (tile >> 4) * 16, x0 = (tile & 15) * 8;

    {
        uint32_t bs0 = smem_u32(Bs);
#pragma unroll
        for (int i = 0; i < 18; i++) {
            int idx = tid + i * 256;
            int tap = idx >> 9, rem = idx & 511;
            int row = rem >> 3, seg = rem & 7;
            cp16(bs0 + (tap * 4608 + row * 72 + seg * 8) * 2,
                 g_wck[which] + tap * 4096 + row * 64 + seg * 8);
        }
        cp_commit();
    }

    if (tid < 64) { sg[tid] = g_gns[b * 64 + tid]; st[tid] = g_gnt[b * 64 + tid]; }
    __syncthreads();

    for (int idx = tid; idx < 1440; idx += 256) {
        int pix = idx >> 3, seg = idx & 7;
        int yy = pix / 10, xx = pix - yy * 10;
        int gy = y0 + yy - 1, gx = x0 + xx - 1;
        uint4 v = make_uint4(0, 0, 0, 0);
        if (gy >= 0 && gy < 128 && gx >= 0 && gx < 128) {
            const float4* sp = (const float4*)(src + (size_t)((b << 14) + (gy << 7) + gx) * 64 + seg * 8);
            float4 r0 = sp[0], r1 = sp[1];
            int cb = seg * 8;
            float o0 = geluf(fmaf(r0.x, sg[cb], st[cb]));
            float o1 = geluf(fmaf(r0.y, sg[cb + 1], st[cb + 1]));
            float o2 = geluf(fmaf(r0.z, sg[cb + 2], st[cb + 2]));
            float o3 = geluf(fmaf(r0.w, sg[cb + 3], st[cb + 3]));
            float o4 = geluf(fmaf(r1.x, sg[cb + 4], st[cb + 4]));
            float o5 = geluf(fmaf(r1.y, sg[cb + 5], st[cb + 5]));
            float o6 = geluf(fmaf(r1.z, sg[cb + 6], st[cb + 6]));
            float o7 = geluf(fmaf(r1.w, sg[cb + 7], st[cb + 7]));
            __nv_bfloat162* vh = (__nv_bfloat162*)&v;
            vh[0] = __floats2bfloat162_rn(o0, o1);
            vh[1] = __floats2bfloat162_rn(o2, o3);
            vh[2] = __floats2bfloat162_rn(o4, o5);
            vh[3] = __floats2bfloat162_rn(o6, o7);
        }
        *(uint4*)(halo + pix * 72 + seg * 8) = v;
    }
    cp_wait<0>();
    __syncthreads();

    float acc[2][4][4];
#pragma unroll
    for (int mt = 0; mt < 2; mt++)
#pragma unroll
        for (int nt = 0; nt < 4; nt++)
#pragma unroll
            for (int j = 0; j < 4; j++) acc[mt][nt][j] = 0.f;

#pragma unroll 1
    for (int tap = 0; tap < 9; tap++) {
        int dy = tap / 3 - 1, dx = tap % 3 - 1;
        const __nv_bfloat16* Bt = Bs + tap * 4608;
#pragma unroll
        for (int ks = 0; ks < 4; ks++) {
            int k0 = ks * 16;
            uint32_t a[2][4], bb[4][2];
#pragma unroll
            for (int mt = 0; mt < 2; mt++) {
                int ry = wm * 4 + mt * 2;
                int p0 = (ry + 1 + dy) * 10 + (g + 1 + dx);
                int p1 = p0 + 10;
                a[mt][0] = *(const uint32_t*)(halo + p0 * 72 + k0 + 2 * t);
                a[mt][1] = *(const uint32_t*)(halo + p1 * 72 + k0 + 2 * t);
                a[mt][2] = *(const uint32_t*)(halo + p0 * 72 + k0 + 2 * t + 8);
                a[mt][3] = *(const uint32_t*)(halo + p1 * 72 + k0 + 2 * t + 8);
            }
#pragma unroll
            for (int nt = 0; nt < 4; nt++) {
                int n = wn * 32 + nt * 8 + g;
                bb[nt][0] = *(const uint32_t*)(Bt + n * 72 + k0 + 2 * t);
                bb[nt][1] = *(const uint32_t*)(Bt + n * 72 + k0 + 2 * t + 8);
            }
#pragma unroll
            for (int mt = 0; mt < 2; mt++)
#pragma unroll
                for (int nt = 0; nt < 4; nt++)
                    mma16816(acc[mt][nt], a[mt], bb[nt]);
        }
    }
#pragma unroll
    for (int mt = 0; mt < 2; mt++) {
        int row = wm * 32 + mt * 16 + g;
        int py = y0 + (row >> 3), px = x0 + (row & 7);
#pragma unroll
        for (int nt = 0; nt < 4; nt++) {
            int col = wn * 32 + nt * 8 + 2 * t;
            float* d1 = dst + (size_t)((b << 14) + (py << 7) + px) * 64 + col;
            *(float2*)d1 = make_float2(acc[mt][nt][0], acc[mt][nt][1]);
            float* d2 = dst + (size_t)((b << 14) + ((py + 1) << 7) + px) * 64 + col;
            *(float2*)d2 = make_float2(acc[mt][nt][2], acc[mt][nt][3]);
        }
    }
    __syncthreads();
    STATS_EPILOGUE(acc, sred, sred2, blockIdx.x)
    gn_finalize(tid, gam, bet);
}

// ---------------- heads ----------------
__global__ void __launch_bounds__(256) k_heads(const float* __restrict__ dw, const float* __restrict__ db,
                                               const float* __restrict__ cwt, const float* __restrict__ cb,
                                               const float* __restrict__ warp, const float* __restrict__ conf,
                                               float* __restrict__ out) {
    __shared__ float sw[3 * 9 * 64];
    int tid = threadIdx.x;
    for (int idx = tid; idx < 1728; idx += 256) {
        int o = idx / 576, rem = idx - o * 576;
        int tap = rem >> 6, c = rem & 63;
        sw[idx] = (o < 2) ? dw[(o * 64 + c) * 9 + tap] : cwt[c * 9 + tap];
    }
    __syncthreads();
    int wr = tid >> 5, lane = tid & 31;
    int p0 = (blockIdx.x * 8 + wr) * 4;
    int b = p0 >> 14, hw = p0 & 16383;
    int y = hw >> 7, x0 = hw & 127;
    int c2 = lane * 2;
    float s0 = g_gns[b * 64 + c2], s1 = g_gns[b * 64 + c2 + 1];
    float t0 = g_gnt[b * 64 + c2], t1 = g_gnt[b * 64 + c2 + 1];

    float nb[3][6][2];
#pragma unroll
    for (int ry = 0; ry < 3; ry++) {
        int yy = y - 1 + ry;
#pragma unroll
        for (int cx = 0; cx < 6; cx++) {
            int xx = x0 - 1 + cx;
            float v0 = 0.f, v1 = 0.f;
            if (yy >= 0 && yy < 128 && xx >= 0 && xx < 128) {
                float2 h = *(const float2*)(g_h1 + (size_t)((b << 14) + (yy << 7) + xx) * 64 + c2);
                v0 = geluf(fmaf(h.x, s0, t0));
                v1 = geluf(fmaf(h.y, s1, t1));
            }
            nb[ry][cx][0] = v0; nb[ry][cx][1] = v1;
        }
    }
    float acc[4][3];
#pragma unroll
    for (int j = 0; j < 4; j++)
#pragma unroll
        for (int o = 0; o < 3; o++) acc[j][o] = 0.f;
#pragma unroll
    for (int ky = 0; ky < 3; ky++)
#pragma unroll
        for (int kx = 0; kx < 3; kx++) {
            int tap = ky * 3 + kx;
            float w0a = sw[tap * 64 + c2], w0b = sw[tap * 64 + c2 + 1];
            float w1a = sw[576 + tap * 64 + c2], w1b = sw[576 + tap * 64 + c2 + 1];
            float w2a = sw[1152 + tap * 64 + c2], w2b = sw[1152 + tap * 64 + c2 + 1];
#pragma unroll
            for (int j = 0; j < 4; j++) {
                float v0 = nb[ky][j + kx][0], v1 = nb[ky][j + kx][1];
                acc[j][0] += w0a * v0 + w0b * v1;
                acc[j][1] += w1a * v0 + w1b * v1;
                acc[j][2] += w2a * v0 + w2b * v1;
            }
        }
#pragma unroll
    for (int o = 16; o; o >>= 1)
#pragma unroll
        for (int j = 0; j < 4; j++) {
            acc[j][0] += __shfl_xor_sync(0xffffffffu, acc[j][0], o);
            acc[j][1] += __shfl_xor_sync(0xffffffffu, acc[j][1], o);
            acc[j][2] += __shfl_xor_sync(0xffffffffu, acc[j][2], o);
        }
    if (lane < 4) {
        int p = p0 + lane;
        float a0 = acc[lane][0], a1 = acc[lane][1], a2 = acc[lane][2];
        float rx = clean15(warp[2 * p]);
        float ry = clean15(warp[2 * p + 1]);
        float fwx = fminf(fmaxf(rx + tanhf(a0 + db[0]) * 0.0625f, -1.5f), 1.5f);
        float fwy = fminf(fmaxf(ry + tanhf(a1 + db[1]) * 0.0625f, -1.5f), 1.5f);
        float cv = conf[p];
        if (!(cv == cv)) cv = 0.f;
        cv = fminf(fmaxf(cv, 0.f), 1.f);
        float pp = fminf(fmaxf(cv, 1e-4f), 1.f - 1e-4f);
        float base = logf(pp) - log1pf(-pp);
        float lg = base + 0.5f * (a2 + cb[0]);
        float rc = fminf(fmaxf(1.f / (1.f + expf(-lg)), 0.f), 1.f);
        out[2 * p] = fwx;
        out[2 * p + 1] = fwy;
        out[65536 + p] = rc;
        out[98304 + p] = lg;
    }
}

extern "C" void kernel_launch(void* const* d_in, const int* in_sizes, int n_in,
                              void* d_out, int out_size) {
    (void)in_sizes; (void)n_in; (void)out_size;
    const float* fA  = (const float*)d_in[0];
    const float* fB  = (const float*)d_in[1];
    const float* cw  = (const float*)d_in[2];
    const float* cf  = (const float*)d_in[3];
    const float* e1w = (const float*)d_in[4];
    const float* g1g = (const float*)d_in[5];
    const float* g1b = (const float*)d_in[6];
    const float* e2w = (const float*)d_in[7];
    const float* g2g = (const float*)d_in[8];
    const float* g2b = (const float*)d_in[9];
    const float* e3w = (const float*)d_in[10];
    const float* g3g = (const float*)d_in[11];
    const float* g3b = (const float*)d_in[12];
    const float* dw  = (const float*)d_in[13];
    const float* db  = (const float*)d_in[14];
    const float* cwt = (const float*)d_in[15];
    const float* cb  = (const float*)d_in[16];
    float* out = (float*)d_out;

    cudaFuncSetAttribute(k_gemm1_mma, cudaFuncAttributeMaxDynamicSharedMemorySize, GEMM_SMEM);
    cudaFuncSetAttribute(k_conv_mma, cudaFuncAttributeMaxDynamicSharedMemorySize, CONV_SMEM);

    k_transpose<<<dim3(512, 4, 4), dim3(32, 8)>>>(fA, fB);
    k_wprep<<<496, 256>>>(e1w, e2w, e3w);
    k_features<<<4096, 256>>>(cw, cf);
    k_gemm1_mma<<<256, 256, GEMM_SMEM>>>(g1g, g1b);
    k_conv_mma<<<256, 256, CONV_SMEM>>>(0, 0, g2g, g2b);   // read g_h1 -> g_h2
    k_conv_mma<<<256, 256, CONV_SMEM>>>(1, 1, g3g, g3b);   // read g_h2 -> g_h1
    k_heads<<<1024, 256>>>(dw, db, cwt, cb, cw, cf, out);
}

// round 11
// speedup vs baseline: 1.2541x; 1.0585x over previous
#include <cuda_runtime.h>
#include <cuda_bf16.h>
#include <math.h>
#include <stdint.h>

#define HWSZ 16384
#define NPIX 32768
#define CC 256

// ---------------- static device scratch ----------------
__device__ __align__(16) __nv_bfloat16 g_fbT[2 * HWSZ * CC];     // feat_B NHWC bf16
__device__ __align__(16) __nv_bfloat16 g_xb[(size_t)NPIX * 832]; // X features bf16 (780 pad->832)
__device__ __align__(16) __nv_bfloat16 g_w1k[13 * 4096];         // enc1 W [chunk][oc][k64]
__device__ __align__(16) __nv_bfloat16 g_wck[2][9 * 4096];       // conv W [tap][oc][ci]
__device__ __align__(16) __nv_bfloat16 g_h1[(size_t)NPIX * 64];  // raw layer out ping (bf16)
__device__ __align__(16) __nv_bfloat16 g_h2[(size_t)NPIX * 64];  // raw layer out pong (bf16)
__device__ float g_gns[128];
__device__ float g_gnt[128];
__device__ float g_pcs[256 * 64];
__device__ float g_pcs2[256 * 64];

__device__ __forceinline__ float clean15(float v) {
    if (!(v == v)) return 0.f;
    return fminf(fmaxf(v, -1.5f), 1.5f);
}
__device__ __forceinline__ float geluf(float z) {
    return 0.5f * z * (1.f + erff(z * 0.70710678118654752f));
}
__device__ __forceinline__ uint32_t smem_u32(const void* p) {
    uint32_t r;
    asm("{ .reg .u64 t; cvta.to.shared.u64 t, %1; cvt.u32.u64 %0, t; }" : "=r"(r) : "l"(p));
    return r;
}
__device__ __forceinline__ void cp16(uint32_t dst, const void* src) {
    asm volatile("cp.async.cg.shared.global [%0], [%1], 16;" :: "r"(dst), "l"(src));
}
__device__ __forceinline__ void cp_commit() {
    asm volatile("cp.async.commit_group;" ::: "memory");
}
template <int N>
__device__ __forceinline__ void cp_wait() {
    asm volatile("cp.async.wait_group %0;" :: "n"(N) : "memory");
}

// bf16 HMMA: D(16x8,f32) += A(16x16,bf16) * B(8x16,bf16)^T
__device__ __forceinline__ void mma16816(float* d, const uint32_t* a, const uint32_t* b) {
    asm volatile(
        "mma.sync.aligned.m16n8k16.row.col.f32.bf16.bf16.f32 "
        "{%0,%1,%2,%3}, {%4,%5,%6,%7}, {%8,%9}, {%0,%1,%2,%3};"
        : "+f"(d[0]), "+f"(d[1]), "+f"(d[2]), "+f"(d[3])
        : "r"(a[0]), "r"(a[1]), "r"(a[2]), "r"(a[3]), "r"(b[0]), "r"(b[1]));
}

// ---------------- K0: NCHW fp32 -> bf16 transpose ----------------
__global__ void k_transpose(const float* __restrict__ fA, const float* __restrict__ fB) {
    __shared__ float tile[64][33];
    int z = blockIdx.z;
    const float* src = (z >= 2) ? fB : fA;
    int b = z & 1;
    src += (size_t)b * CC * HWSZ;
    __nv_bfloat16* dstbase;
    size_t stride;
    if (z < 2) { dstbase = g_xb + (size_t)(b << 14) * 832; stride = 832; }
    else       { dstbase = g_fbT + ((size_t)(b << 14) << 8); stride = 256; }
    int hw0 = blockIdx.x * 32, c0 = blockIdx.y * 64;
    int tx = threadIdx.x, ty = threadIdx.y;          // (32,8)
#pragma unroll
    for (int i = 0; i < 8; i++) {
        int cr = ty + i * 8;
        tile[cr][tx] = src[(c0 + cr) * HWSZ + hw0 + tx];
    }
    __syncthreads();
#pragma unroll
    for (int i = 0; i < 4; i++) {
        int r = ty + i * 8;
        __nv_bfloat162 v = __floats2bfloat162_rn(tile[2 * tx][r], tile[2 * tx + 1][r]);
        *(__nv_bfloat162*)(dstbase + (size_t)(hw0 + r) * stride + c0 + 2 * tx) = v;
    }
}

// ---------------- weight prep ----------------
__global__ void k_wprep(const float* __restrict__ w1, const float* __restrict__ w2,
                        const float* __restrict__ w3) {
    int blk = blockIdx.x;
    if (blk < 208) {
        int idx = blk * 256 + threadIdx.x;
        if (idx >= 13 * 4096) return;
        int chunk = idx >> 12, rem = idx & 4095;
        int oc = rem >> 6, k = rem & 63;
        int kg = chunk * 64 + k;
        g_w1k[idx] = __float2bfloat16((kg < 780) ? w1[oc * 780 + kg] : 0.f);
    } else {
        int which = (blk < 352) ? 0 : 1;
        const float* w = which ? w3 : w2;
        int idx = (blk - (which ? 352 : 208)) * 256 + threadIdx.x;
        if (idx >= 9 * 4096) return;
        int tap = idx >> 12, rem = idx & 4095;
        int oc = rem >> 6, ci = rem & 63;
        g_wck[which][idx] = __float2bfloat16(w[(oc * 64 + ci) * 9 + tap]);
    }
}

// ---------------- K1: per-pixel features ----------------
__global__ void __launch_bounds__(256) k_features(const float* __restrict__ cw,
                                                  const float* __restrict__ cf) {
    int p = blockIdx.x * 8 + (threadIdx.x >> 5);
    int lane = threadIdx.x & 31;
    int b = p >> 14, hw = p & 16383;
    int py = hw >> 7, px = hw & 127;

    float gx = clean15(cw[2 * p]);
    float gy = clean15(cw[2 * p + 1]);
    float xc = fmaf(gx, 64.f, 63.5f);
    float yc = fmaf(gy, 64.f, 63.5f);
    float x0f = floorf(xc), y0f = floorf(yc);
    float wx = xc - x0f, wy = yc - y0f;
    float iwx = 1.f - wx, iwy = 1.f - wy;
    int x0 = (int)x0f, y0 = (int)y0f;

    __nv_bfloat16* xrow = g_xb + (size_t)p * 832;
    int c = lane * 8;

    uint4 cU[4][4];
#pragma unroll
    for (int t = 0; t < 4; t++) {
        int cyp = min(max(y0 - 1 + t, 0), 127);
#pragma unroll
        for (int u = 0; u < 4; u++) {
            int cxp = min(max(x0 - 1 + u, 0), 127);
            cU[t][u] = *(const uint4*)(g_fbT + ((((b << 14) + (cyp << 7) + cxp) << 8) + c));
        }
    }
    uint4 faU = *(const uint4*)(xrow + c);

    float fav[8];
    {
        const __nv_bfloat162* h = (const __nv_bfloat162*)&faU;
#pragma unroll
        for (int j = 0; j < 4; j++) {
            float2 f = __bfloat1622float2(h[j]);
            fav[2 * j] = f.x; fav[2 * j + 1] = f.y;
        }
    }
    float na = 0.f, ns[9], dt[9];
#pragma unroll
    for (int s = 0; s < 9; s++) { ns[s] = 0.f; dt[s] = 0.f; }
#pragma unroll
    for (int j = 0; j < 8; j++) na += fav[j] * fav[j];

    float lxp[3][8];
    float wv[8];
#pragma unroll
    for (int t = 0; t < 4; t++) {
        float cv[4][8];
#pragma unroll
        for (int u = 0; u < 4; u++) {
            const __nv_bfloat162* h = (const __nv_bfloat162*)&cU[t][u];
#pragma unroll
            for (int j = 0; j < 4; j++) {
                float2 f = __bfloat1622float2(h[j]);
                cv[u][2 * j] = f.x; cv[u][2 * j + 1] = f.y;
            }
        }
        float lx[3][8];
#pragma unroll
        for (int j = 0; j < 8; j++) {
            lx[0][j] = cv[0][j] * iwx + cv[1][j] * wx;
            lx[1][j] = cv[1][j] * iwx + cv[2][j] * wx;
            lx[2][j] = cv[2][j] * iwx + cv[3][j] * wx;
        }
        if (t > 0) {
            int dyrow = t - 1;
#pragma unroll
            for (int i = 0; i < 3; i++) {
                int s = dyrow * 3 + i;
#pragma unroll
                for (int j = 0; j < 8; j++) {
                    float v = lxp[i][j] * iwy + lx[i][j] * wy;
                    ns[s] += v * v;
                    dt[s] += fav[j] * v;
                    if (dyrow == 1 && i == 1) wv[j] = v;
                }
            }
        }
#pragma unroll
        for (int i = 0; i < 3; i++)
#pragma unroll
            for (int j = 0; j < 8; j++) lxp[i][j] = lx[i][j];
    }
    {
        uint4 W, D;
        __nv_bfloat162* wh = (__nv_bfloat162*)&W;
        __nv_bfloat162* dh = (__nv_bfloat162*)&D;
#pragma unroll
        for (int j = 0; j < 4; j++) {
            wh[j] = __floats2bfloat162_rn(wv[2 * j], wv[2 * j + 1]);
            dh[j] = __floats2bfloat162_rn(fabsf(fav[2 * j] - wv[2 * j]),
                                          fabsf(fav[2 * j + 1] - wv[2 * j + 1]));
        }
        *(uint4*)(xrow + 256 + c) = W;
        *(uint4*)(xrow + 512 + c) = D;
    }

#pragma unroll
    for (int o = 16; o; o >>= 1) {
        na += __shfl_xor_sync(0xffffffffu, na, o);
#pragma unroll
        for (int s = 0; s < 9; s++) {
            ns[s] += __shfl_xor_sync(0xffffffffu, ns[s], o);
            dt[s] += __shfl_xor_sync(0xffffffffu, dt[s], o);
        }
    }
    if (lane == 0) {
        float sna = fmaxf(sqrtf(na), 1e-12f);
        float dispx = gx - ((px + 0.5f) * (2.f / 128.f) - 1.f);
        float dispy = gy - ((py + 0.5f) * (2.f / 128.f) - 1.f);
        float cfv = cf[p];
        if (!(cfv == cfv)) cfv = 0.f;
        cfv = fminf(fmaxf(cfv, 0.f), 1.f);
        xrow[768] = __float2bfloat16(dispx);
        xrow[769] = __float2bfloat16(dispy);
        xrow[770] = __float2bfloat16(cfv);
#pragma unroll
        for (int s = 0; s < 9; s++)
            xrow[771 + s] = __float2bfloat16(dt[s] / (sna * fmaxf(sqrtf(ns[s]), 1e-12f)));
    } else if (lane <= 13) {
        ((uint2*)(xrow + 780))[lane - 1] = make_uint2(0u, 0u);
    }
}

// ---------------- shared epilogue: per-CTA (sum, sumsq) per channel ----------------
#define STATS_EPILOGUE(ACC, SRED, SRED2, SLOT)                                        \
    {                                                                                 \
        float ps[4][2], pq[4][2];                                                     \
        _Pragma("unroll")                                                             \
        for (int nt = 0; nt < 4; nt++) {                                              \
            float v0 = ACC[0][nt][0], v1 = ACC[0][nt][2],                             \
                  v2 = ACC[1][nt][0], v3 = ACC[1][nt][2];                             \
            ps[nt][0] = v0 + v1 + v2 + v3;                                            \
            pq[nt][0] = v0 * v0 + v1 * v1 + v2 * v2 + v3 * v3;                        \
            float u0 = ACC[0][nt][1], u1 = ACC[0][nt][3],                             \
                  u2 = ACC[1][nt][1], u3 = ACC[1][nt][3];                             \
            ps[nt][1] = u0 + u1 + u2 + u3;                                            \
            pq[nt][1] = u0 * u0 + u1 * u1 + u2 * u2 + u3 * u3;                        \
        }                                                                             \
        _Pragma("unroll")                                                             \
        for (int o = 4; o <= 16; o <<= 1)                                             \
            _Pragma("unroll")                                                         \
            for (int nt = 0; nt < 4; nt++)                                            \
                _Pragma("unroll")                                                     \
                for (int pr = 0; pr < 2; pr++) {                                      \
                    ps[nt][pr] += __shfl_xor_sync(0xffffffffu, ps[nt][pr], o);        \
                    pq[nt][pr] += __shfl_xor_sync(0xffffffffu, pq[nt][pr], o);        \
                }                                                                     \
        if (lane < 4) {                                                               \
            _Pragma("unroll")                                                         \
            for (int nt = 0; nt < 4; nt++)                                            \
                _Pragma("unroll")                                                     \
                for (int pr = 0; pr < 2; pr++) {                                      \
                    SRED[warp][nt * 8 + 2 * lane + pr] = ps[nt][pr];                  \
                    SRED2[warp][nt * 8 + 2 * lane + pr] = pq[nt][pr];                 \
                }                                                                     \
        }                                                                             \
        __syncthreads();                                                              \
        if (tid < 64) {                                                               \
            int wn2 = tid >> 5, j2 = tid & 31;                                        \
            float ssum = 0.f, qsum = 0.f;                                             \
            _Pragma("unroll")                                                         \
            for (int wm2 = 0; wm2 < 4; wm2++) {                                       \
                ssum += SRED[wn2 * 4 + wm2][j2];                                      \
                qsum += SRED2[wn2 * 4 + wm2][j2];                                     \
            }                                                                         \
            g_pcs[(size_t)(SLOT) * 64 + wn2 * 32 + j2] = ssum;                        \
            g_pcs2[(size_t)(SLOT) * 64 + wn2 * 32 + j2] = qsum;                       \
        }                                                                             \
    }

// ---------------- enc1 GEMM: 4-stage cp.async pipeline ----------------
#define GEMM_SMEM (4 * 9216 * 2 + 4 * 4608 * 2)
__global__ void __launch_bounds__(256) k_gemm1_mma() {
    extern __shared__ __nv_bfloat16 dyn[];
    __nv_bfloat16* As = dyn;               // [4][128*72]
    __nv_bfloat16* Bs = dyn + 4 * 9216;    // [4][64*72]
    __shared__ float sred[8][32], sred2[8][32];
    int tid = threadIdx.x;
    int warp = tid >> 5, lane = tid & 31;
    int g = lane >> 2, t = lane & 3;
    int wm = warp & 3, wn = warp >> 2;
    float acc[2][4][4];
#pragma unroll
    for (int mt = 0; mt < 2; mt++)
#pragma unroll
        for (int nt = 0; nt < 4; nt++)
#pragma unroll
            for (int j = 0; j < 4; j++) acc[mt][nt][j] = 0.f;

    int pix0 = blockIdx.x * 128;
    int arow = tid >> 1, acol = (tid & 1) * 32;
    const __nv_bfloat16* asrc0 = g_xb + (size_t)(pix0 + arow) * 832 + acol;
    uint32_t adst0 = smem_u32(As + arow * 72 + acol);
    int brow0 = tid >> 3, bseg = (tid & 7) * 8;
    uint32_t bdst0 = smem_u32(Bs + brow0 * 72 + bseg);
    const __nv_bfloat16* bsrc0 = g_w1k + brow0 * 64 + bseg;

    auto load_chunk = [&](int chunk) {
        int buf = chunk & 3;
        uint32_t ad = adst0 + buf * 9216 * 2;
        const __nv_bfloat16* as = asrc0 + chunk * 64;
#pragma unroll
        for (int j = 0; j < 4; j++)
            cp16(ad + j * 16, as + j * 8);
        uint32_t bd = bdst0 + buf * 4608 * 2;
        const __nv_bfloat16* bs = bsrc0 + chunk * 4096;
        cp16(bd, bs);
        cp16(bd + 32 * 72 * 2, bs + 32 * 64);
    };

    load_chunk(0); cp_commit();
    load_chunk(1); cp_commit();
    load_chunk(2); cp_commit();
    for (int chunk = 0; chunk < 13; chunk++) {
        if (chunk + 3 < 13) load_chunk(chunk + 3);
        cp_commit();
        cp_wait<3>();
        __syncthreads();
        int buf = chunk & 3;
        const __nv_bfloat16* Ab = As + buf * 9216;
        const __nv_bfloat16* Bb = Bs + buf * 4608;
#pragma unroll
        for (int ks = 0; ks < 4; ks++) {
            int k0 = ks * 16;
            uint32_t a[2][4], bb[4][2];
#pragma unroll
            for (int mt = 0; mt < 2; mt++) {
                int row0 = wm * 32 + mt * 16 + g;
                a[mt][0] = *(const uint32_t*)(Ab + row0 * 72 + k0 + 2 * t);
                a[mt][1] = *(const uint32_t*)(Ab + (row0 + 8) * 72 + k0 + 2 * t);
                a[mt][2] = *(const uint32_t*)(Ab + row0 * 72 + k0 + 2 * t + 8);
                a[mt][3] = *(const uint32_t*)(Ab + (row0 + 8) * 72 + k0 + 2 * t + 8);
            }
#pragma unroll
            for (int nt = 0; nt < 4; nt++) {
                int n = wn * 32 + nt * 8 + g;
                bb[nt][0] = *(const uint32_t*)(Bb + n * 72 + k0 + 2 * t);
                bb[nt][1] = *(const uint32_t*)(Bb + n * 72 + k0 + 2 * t + 8);
            }
#pragma unroll
            for (int mt = 0; mt < 2; mt++)
#pragma unroll
                for (int nt = 0; nt < 4; nt++)
                    mma16816(acc[mt][nt], a[mt], bb[nt]);
        }
        __syncthreads();
    }
#pragma unroll
    for (int mt = 0; mt < 2; mt++) {
        int row = wm * 32 + mt * 16 + g;
#pragma unroll
        for (int nt = 0; nt < 4; nt++) {
            int col = wn * 32 + nt * 8 + 2 * t;
            *(__nv_bfloat162*)(g_h1 + (size_t)(pix0 + row) * 64 + col) =
                __floats2bfloat162_rn(acc[mt][nt][0], acc[mt][nt][1]);
            *(__nv_bfloat162*)(g_h1 + (size_t)(pix0 + row + 8) * 64 + col) =
                __floats2bfloat162_rn(acc[mt][nt][2], acc[mt][nt][3]);
        }
    }
    __syncthreads();
    STATS_EPILOGUE(acc, sred, sred2, blockIdx.x)
}

// ---------------- 3x3 conv: bf16 h in/out, GN+GELU fused ----------------
#define CONV_SMEM (180 * 72 * 2 + 9 * 64 * 72 * 2)
__global__ void __launch_bounds__(256) k_conv_mma(int which, int srcsel) {
    extern __shared__ __nv_bfloat16 sm[];
    __nv_bfloat16* halo = sm;                 // [pix 180][72]
    __nv_bfloat16* Bs = sm + 180 * 72;        // [tap 9][64][72]
    __shared__ float sg[64], st[64];
    __shared__ float sred[8][32], sred2[8][32];
    const __nv_bfloat16* src = srcsel ? g_h2 : g_h1;
    __nv_bfloat16* dst = srcsel ? g_h1 : g_h2;
    int tid = threadIdx.x;
    int warp = tid >> 5, lane = tid & 31;
    int g = lane >> 2, t = lane & 3;
    int wm = warp & 3, wn = warp >> 2;
    int b = blockIdx.x >> 7;
    int tile = blockIdx.x & 127;
    int y0 = (tile >> 4) * 16, x0 = (tile & 15) * 8;

    {
        uint32_t bs0 = smem_u32(Bs);
#pragma unroll
        for (int i = 0; i < 18; i++) {
            int idx = tid + i * 256;
            int tap = idx >> 9, rem = idx & 511;
            int row = rem >> 3, seg = rem & 7;
            cp16(bs0 + (tap * 4608 + row * 72 + seg * 8) * 2,
                 g_wck[which] + tap * 4096 + row * 64 + seg * 8);
        }
        cp_commit();
    }

    if (tid < 64) { sg[tid] = g_gns[b * 64 + tid]; st[tid] = g_gnt[b * 64 + tid]; }
    __syncthreads();

    for (int idx = tid; idx < 1440; idx += 256) {
        int pix = idx >> 3, seg = idx & 7;
        int yy = pix / 10, xx = pix - yy * 10;
        int gy = y0 + yy - 1, gx = x0 + xx - 1;
        uint4 v = make_uint4(0, 0, 0, 0);
        if (gy >= 0 && gy < 128 && gx >= 0 && gx < 128) {
            uint4 raw = *(const uint4*)(src + (size_t)((b << 14) + (gy << 7) + gx) * 64 + seg * 8);
            const __nv_bfloat162* rh = (const __nv_bfloat162*)&raw;
            int cb = seg * 8;
            __nv_bfloat162* vh = (__nv_bfloat162*)&v;
#pragma unroll
            for (int j = 0; j < 4; j++) {
                float2 f = __bfloat1622float2(rh[j]);
                float o0 = geluf(fmaf(f.x, sg[cb + 2 * j], st[cb + 2 * j]));
                float o1 = geluf(fmaf(f.y, sg[cb + 2 * j + 1], st[cb + 2 * j + 1]));
                vh[j] = __floats2bfloat162_rn(o0, o1);
            }
        }
        *(uint4*)(halo + pix * 72 + seg * 8) = v;
    }
    cp_wait<0>();
    __syncthreads();

    float acc[2][4][4];
#pragma unroll
    for (int mt = 0; mt < 2; mt++)
#pragma unroll
        for (int nt = 0; nt < 4; nt++)
#pragma unroll
            for (int j = 0; j < 4; j++) acc[mt][nt][j] = 0.f;

#pragma unroll 1
    for (int tap = 0; tap < 9; tap++) {
        int dy = tap / 3 - 1, dx = tap % 3 - 1;
        const __nv_bfloat16* Bt = Bs + tap * 4608;
#pragma unroll
        for (int ks = 0; ks < 4; ks++) {
            int k0 = ks * 16;
            uint32_t a[2][4], bb[4][2];
#pragma unroll
            for (int mt = 0; mt < 2; mt++) {
                int ry = wm * 4 + mt * 2;
                int p0 = (ry + 1 + dy) * 10 + (g + 1 + dx);
                int p1 = p0 + 10;
                a[mt][0] = *(const uint32_t*)(halo + p0 * 72 + k0 + 2 * t);
                a[mt][1] = *(const uint32_t*)(halo + p1 * 72 + k0 + 2 * t);
                a[mt][2] = *(const uint32_t*)(halo + p0 * 72 + k0 + 2 * t + 8);
                a[mt][3] = *(const uint32_t*)(halo + p1 * 72 + k0 + 2 * t + 8);
            }
#pragma unroll
            for (int nt = 0; nt < 4; nt++) {
                int n = wn * 32 + nt * 8 + g;
                bb[nt][0] = *(const uint32_t*)(Bt + n * 72 + k0 + 2 * t);
                bb[nt][1] = *(const uint32_t*)(Bt + n * 72 + k0 + 2 * t + 8);
            }
#pragma unroll
            for (int mt = 0; mt < 2; mt++)
#pragma unroll
                for (int nt = 0; nt < 4; nt++)
                    mma16816(acc[mt][nt], a[mt], bb[nt]);
        }
    }
#pragma unroll
    for (int mt = 0; mt < 2; mt++) {
        int row = wm * 32 + mt * 16 + g;
        int py = y0 + (row >> 3), px = x0 + (row & 7);
#pragma unroll
        for (int nt = 0; nt < 4; nt++) {
            int col = wn * 32 + nt * 8 + 2 * t;
            *(__nv_bfloat162*)(dst + (size_t)((b << 14) + (py << 7) + px) * 64 + col) =
                __floats2bfloat162_rn(acc[mt][nt][0], acc[mt][nt][1]);
            *(__nv_bfloat162*)(dst + (size_t)((b << 14) + ((py + 1) << 7) + px) * 64 + col) =
                __floats2bfloat162_rn(acc[mt][nt][2], acc[mt][nt][3]);
        }
    }
    __syncthreads();
    STATS_EPILOGUE(acc, sred, sred2, blockIdx.x)
}

// ---------------- GN stats stage 2: grid 16 (one CTA per batch,group) ----------------
__global__ void k_stats2(const float* __restrict__ gam, const float* __restrict__ bet) {
    int bg = blockIdx.x;               // 0..15
    int b = bg >> 3, g = bg & 7;
    int tid = threadIdx.x;             // 256
    int c8 = tid & 7, sl = tid >> 3;   // 32 slot-groups of 4
    int c = g * 8 + c8;
    float s = 0.f, q = 0.f;
#pragma unroll
    for (int i = 0; i < 4; i++) {
        int slot = b * 128 + sl * 4 + i;
        s += g_pcs[(size_t)slot * 64 + c];
        q += g_pcs2[(size_t)slot * 64 + c];
    }
    __shared__ float ss[32][8], qq[32][8];
    ss[sl][c8] = s; qq[sl][c8] = q;
    __syncthreads();
    for (int o = 16; o; o >>= 1) {
        if (sl < o) { ss[sl][c8] += ss[sl + o][c8]; qq[sl][c8] += qq[sl + o][c8]; }
        __syncthreads();
    }
    if (tid < 8) {
        float gs = 0.f, gq = 0.f;
#pragma unroll
        for (int j = 0; j < 8; j++) { gs += ss[0][j]; gq += qq[0][j]; }
        float mu = gs * (1.f / 131072.f);
        float var = gq * (1.f / 131072.f) - mu * mu;
        int cc = g * 8 + tid;
        float sc = gam[cc] * rsqrtf(var + 1e-5f);
        g_gns[b * 64 + cc] = sc;
        g_gnt[b * 64 + cc] = bet[cc] - mu * sc;
    }
}

// ---------------- heads: bf16 h input ----------------
__global__ void __launch_bounds__(256) k_heads(const float* __restrict__ dw, const float* __restrict__ db,
                                               const float* __restrict__ cwt, const float* __restrict__ cb,
                                               const float* __restrict__ warp, const float* __restrict__ conf,
                                               float* __restrict__ out) {
    __shared__ float sw[3 * 9 * 64];
    int tid = threadIdx.x;
    for (int idx = tid; idx < 1728; idx += 256) {
        int o = idx / 576, rem = idx - o * 576;
        int tap = rem >> 6, c = rem & 63;
        sw[idx] = (o < 2) ? dw[(o * 64 + c) * 9 + tap] : cwt[c * 9 + tap];
    }
    __syncthreads();
    int wr = tid >> 5, lane = tid & 31;
    int p0 = (blockIdx.x * 8 + wr) * 4;
    int b = p0 >> 14, hw = p0 & 16383;
    int y = hw >> 7, x0 = hw & 127;
    int c2 = lane * 2;
    float s0 = g_gns[b * 64 + c2], s1 = g_gns[b * 64 + c2 + 1];
    float t0 = g_gnt[b * 64 + c2], t1 = g_gnt[b * 64 + c2 + 1];

    float nb[3][6][2];
#pragma unroll
    for (int ry = 0; ry < 3; ry++) {
        int yy = y - 1 + ry;
#pragma unroll
        for (int cx = 0; cx < 6; cx++) {
            int xx = x0 - 1 + cx;
            float v0 = 0.f, v1 = 0.f;
            if (yy >= 0 && yy < 128 && xx >= 0 && xx < 128) {
                __nv_bfloat162 h = *(const __nv_bfloat162*)(g_h1 + (size_t)((b << 14) + (yy << 7) + xx) * 64 + c2);
                float2 f = __bfloat1622float2(h);
                v0 = geluf(fmaf(f.x, s0, t0));
                v1 = geluf(fmaf(f.y, s1, t1));
            }
            nb[ry][cx][0] = v0; nb[ry][cx][1] = v1;
        }
    }
    float acc[4][3];
#pragma unroll
    for (int j = 0; j < 4; j++)
#pragma unroll
        for (int o = 0; o < 3; o++) acc[j][o] = 0.f;
#pragma unroll
    for (int ky = 0; ky < 3; ky++)
#pragma unroll
        for (int kx = 0; kx < 3; kx++) {
            int tap = ky * 3 + kx;
            float w0a = sw[tap * 64 + c2], w0b = sw[tap * 64 + c2 + 1];
            float w1a = sw[576 + tap * 64 + c2], w1b = sw[576 + tap * 64 + c2 + 1];
            float w2a = sw[1152 + tap * 64 + c2], w2b = sw[1152 + tap * 64 + c2 + 1];
#pragma unroll
            for (int j = 0; j < 4; j++) {
                float v0 = nb[ky][j + kx][0], v1 = nb[ky][j + kx][1];
                acc[j][0] += w0a * v0 + w0b * v1;
                acc[j][1] += w1a * v0 + w1b * v1;
                acc[j][2] += w2a * v0 + w2b * v1;
            }
        }
#pragma unroll
    for (int o = 16; o; o >>= 1)
#pragma unroll
        for (int j = 0; j < 4; j++) {
            acc[j][0] += __shfl_xor_sync(0xffffffffu, acc[j][0], o);
            acc[j][1] += __shfl_xor_sync(0xffffffffu, acc[j][1], o);
            acc[j][2] += __shfl_xor_sync(0xffffffffu, acc[j][2], o);
        }
    if (lane < 4) {
        int p = p0 + lane;
        float a0 = acc[lane][0], a1 = acc[lane][1], a2 = acc[lane][2];
        float rx = clean15(warp[2 * p]);
        float ry = clean15(warp[2 * p + 1]);
        float fwx = fminf(fmaxf(rx + tanhf(a0 + db[0]) * 0.0625f, -1.5f), 1.5f);
        float fwy = fminf(fmaxf(ry + tanhf(a1 + db[1]) * 0.0625f, -1.5f), 1.5f);
        float cv = conf[p];
        if (!(cv == cv)) cv = 0.f;
        cv = fminf(fmaxf(cv, 0.f), 1.f);
        float pp = fminf(fmaxf(cv, 1e-4f), 1.f - 1e-4f);
        float base = logf(pp) - log1pf(-pp);
        float lg = base + 0.5f * (a2 + cb[0]);
        float rc = fminf(fmaxf(1.f / (1.f + expf(-lg)), 0.f), 1.f);
        out[2 * p] = fwx;
        out[2 * p + 1] = fwy;
        out[65536 + p] = rc;
        out[98304 + p] = lg;
    }
}

extern "C" void kernel_launch(void* const* d_in, const int* in_sizes, int n_in,
                              void* d_out, int out_size) {
    (void)in_sizes; (void)n_in; (void)out_size;
    const float* fA  = (const float*)d_in[0];
    const float* fB  = (const float*)d_in[1];
    const float* cw  = (const float*)d_in[2];
    const float* cf  = (const float*)d_in[3];
    const float* e1w = (const float*)d_in[4];
    const float* g1g = (const float*)d_in[5];
    const float* g1b = (const float*)d_in[6];
    const float* e2w = (const float*)d_in[7];
    const float* g2g = (const float*)d_in[8];
    const float* g2b = (const float*)d_in[9];
    const float* e3w = (const float*)d_in[10];
    const float* g3g = (const float*)d_in[11];
    const float* g3b = (const float*)d_in[12];
    const float* dw  = (const float*)d_in[13];
    const float* db  = (const float*)d_in[14];
    const float* cwt = (const float*)d_in[15];
    const float* cb  = (const float*)d_in[16];
    float* out = (float*)d_out;

    cudaFuncSetAttribute(k_gemm1_mma, cudaFuncAttributeMaxDynamicSharedMemorySize, GEMM_SMEM);
    cudaFuncSetAttribute(k_conv_mma, cudaFuncAttributeMaxDynamicSharedMemorySize, CONV_SMEM);

    k_transpose<<<dim3(512, 4, 4), dim3(32, 8)>>>(fA, fB);
    k_wprep<<<496, 256>>>(e1w, e2w, e3w);
    k_features<<<4096, 256>>>(cw, cf);
    k_gemm1_mma<<<256, 256, GEMM_SMEM>>>();
    k_stats2<<<16, 256>>>(g1g, g1b);
    k_conv_mma<<<256, 256, CONV_SMEM>>>(0, 0);   // read g_h1 -> g_h2
    k_stats2<<<16, 256>>>(g2g, g2b);
    k_conv_mma<<<256, 256, CONV_SMEM>>>(1, 1);   // read g_h2 -> g_h1
    k_stats2<<<16, 256>>>(g3g, g3b);
    k_heads<<<1024, 256>>>(dw, db, cwt, cb, cw, cf, out);
}